// round 9
// baseline (speedup 1.0000x reference)
#include <cuda_runtime.h>

// Cost volume s2: B=4, C=32, H=W=256, D=9, 8 groups of 4 channels.
// y-offset 0 -> 1D lerp in x; res span 0.8 < 1 px -> 3 taps/side cover all d.
// F folded into the lerp: a = wl-F = (P1-F) + t*S + |t|*Dd.
// Pairwise variance: cost = (1/18) * Sum_ci( a^2 + b^2 - a*b ),  b = wr-F.
// Block = one (b, row h, group PAIR). L/R rows staged in SMEM (coalesced
// float4); F read DIRECTLY from global (it's only needed at [w]=tid, fully
// coalesced) and prefetched before the sync so its latency overlaps staging.
// launch_bounds(256,5): regs<=51 -> 5 blocks/SM -> 40 warps (62.5% occ).

typedef unsigned long long u64;

constexpr int Wd = 256, Cn = 32, Bn = 4, Dn = 9, Gn = 8, CPG = 4;
constexpr int HW = 256 * 256;
constexpr int RW = 268;          // padded SMEM row: 4 halo + 256 + 8 halo
constexpr int GPB = 2;           // groups per block
constexpr int CB  = GPB * CPG;   // 8 channels staged per block

__device__ __forceinline__ u64 pk(float a, float b) {
    u64 r; asm("mov.b64 %0, {%1, %2};" : "=l"(r) : "f"(a), "f"(b)); return r;
}
__device__ __forceinline__ void upk(float& a, float& b, u64 v) {
    asm("mov.b64 {%0, %1}, %2;" : "=f"(a), "=f"(b) : "l"(v));
}
__device__ __forceinline__ u64 ffma2(u64 a, u64 b, u64 c) {
    u64 d; asm("fma.rn.f32x2 %0, %1, %2, %3;" : "=l"(d) : "l"(a), "l"(b), "l"(c));
    return d;
}
__device__ __forceinline__ u64 add2(u64 a, u64 b) {
    u64 d; asm("add.rn.f32x2 %0, %1, %2;" : "=l"(d) : "l"(a), "l"(b));
    return d;
}

__global__ __launch_bounds__(256, 5) void cost_volume_kernel(
    const float* __restrict__ fref,
    const float* __restrict__ fls,
    const float* __restrict__ frs,
    const float* __restrict__ dinit,
    float* __restrict__ out)
{
    __shared__ float sL[CB][RW];
    __shared__ float sR[CB][RW];

    const int bid = blockIdx.x;          // B*H*(G/2) = 4096 blocks
    const int gp = bid & 3;              // group pair 0..3
    const int h  = (bid >> 2) & 255;
    const int b  = bid >> 10;
    const int tid = threadIdx.x;
    const int w = tid;

    // ---- Zero halos: 16 rows (8 L + 8 R) x 12 entries ----
    if (tid < 192) {
        const int r   = tid / 12;              // 0..15 : (ci8, arr)
        const int e   = tid % 12;
        const int off = (e < 4) ? e : (256 + e);
        float (*A)[RW] = (r & 1) ? sR : sL;
        A[r >> 1][off] = 0.0f;
    }

    const int rowg0 = b * Cn * HW + gp * CB * HW + h * 256;

    // ---- Stage 16 rows (8ch x {L,R}) as 1024 float4, 4 per thread ----
    #pragma unroll
    for (int k = 0; k < 4; k++) {
        const int j     = tid + (k << 8);
        const int which = j >> 6;              // 0..15
        const int col4  = j & 63;
        const int ci8   = which & 7;
        const float* src = (which & 8) ? frs : fls;
        const float4 v = __ldg((const float4*)(src + rowg0 + ci8 * HW) + col4);
        if (which & 8) *(float4*)&sR[ci8][4 + (col4 << 2)] = v;
        else           *(float4*)&sL[ci8][4 + (col4 << 2)] = v;
    }

    // ---- Direct (coalesced) loads that don't need SMEM: F taps + disp ----
    float Fv[CB];
    #pragma unroll
    for (int c8 = 0; c8 < CB; c8++)
        Fv[c8] = __ldg(fref + rowg0 + c8 * HW + w);

    const float disp = __ldg(dinit + b * HW + h * 256 + w);
    const float wf = (float)w;

    // Left taps n_l..n_l+2, n_l = floor(x_l at d=0); x_l increases with d.
    const float xl0 = wf + disp - 0.4f;
    const float fll = floorf(xl0);
    const int   n_l = (int)fll;
    const float tl0 = xl0 - fll - 1.0f;
    // Right taps n_r..n_r+2, n_r = floor(x_r at d=8); x_r decreases with d.
    const float xr0 = wf - disp + 0.4f;
    const float flr = floorf(xr0 - 0.8f);
    const int   n_r = (int)flr;
    const float tr0 = xr0 - flr - 1.0f;

    const u64 t02   = pk(tl0, tr0);
    const u64 step2 = pk(0.1f, -0.1f);
    const u64 amask = 0x7FFFFFFF7FFFFFFFull;
    const int il = n_l + 4;
    const int ir = n_r + 4;
    const float c18 = 1.0f / 18.0f;

    __syncthreads();

    float* outbh = out + b * (Gn * Dn * HW) + gp * GPB * Dn * HW + h * 256 + w;

    #pragma unroll 1
    for (int gg = 0; gg < GPB; gg++) {
        // ---- Gather taps, build packed operands (F pre-subtracted) ----
        u64 P1F[CPG], Sv[CPG], Dd[CPG];
        #pragma unroll
        for (int ci = 0; ci < CPG; ci++) {
            const int c8 = gg * CPG + ci;
            const float L0 = sL[c8][il], L1 = sL[c8][il + 1], L2 = sL[c8][il + 2];
            const float R0 = sR[c8][ir], R1 = sR[c8][ir + 1], R2 = sR[c8][ir + 2];
            const float F  = Fv[c8];

            P1F[ci] = pk(L1 - F, R1 - F);
            Sv[ci]  = pk(0.5f * (L2 - L0), 0.5f * (R2 - R0));
            Dd[ci]  = pk(fmaf(0.5f, L2 + L0, -L1), fmaf(0.5f, R2 + R0, -R1));
        }

        float* outp = outbh + gg * Dn * HW;
        u64 t2 = t02;

        #pragma unroll
        for (int d = 0; d < 9; d++) {
            const u64 at2 = t2 & amask;        // (|t_l|, |t_r|)

            u64 accP = 0ull;
            float ax = 0.0f;
            #pragma unroll
            for (int ci = 0; ci < CPG; ci++) {
                const u64 lw = ffma2(t2, Sv[ci],
                               ffma2(at2, Dd[ci], P1F[ci]));
                accP = ffma2(lw, lw, accP);    // (S a^2, S b^2)
                float a, bb; upk(a, bb, lw);
                ax = fmaf(a, bb, ax);          // S a*b
            }
            t2 = add2(t2, step2);

            float aPl, aPr; upk(aPl, aPr, accP);
            __stcg(outp + d * HW, ((aPl + aPr) - ax) * c18);
        }
    }
}

extern "C" void kernel_launch(void* const* d_in, const int* in_sizes, int n_in,
                              void* d_out, int out_size)
{
    const float* fref  = (const float*)d_in[0];
    const float* fls   = (const float*)d_in[1];
    const float* frs   = (const float*)d_in[2];
    const float* dinit = (const float*)d_in[3];
    float* out = (float*)d_out;

    // blocks over (b, h, group-pair): 4 * 256 * 4 = 4096
    cost_volume_kernel<<<Bn * 256 * (Gn / GPB), 256>>>(fref, fls, frs, dinit, out);
}